// round 1
// baseline (speedup 1.0000x reference)
#include <cuda_runtime.h>
#include <math.h>

#define SEQ 2048
#define DIM 4096
#define NH 32
#define NKV 8
#define HD 128
#define KVD (NKV*HD)   // 1024

// ---- scratch (no cudaMalloc allowed) ----
__device__ float g_q[SEQ * DIM];            // 32 MB
__device__ float g_k[SEQ * KVD];            // 8 MB
__device__ float g_v[SEQ * KVD];            // 8 MB
__device__ float g_attn[SEQ * DIM];         // 32 MB
__device__ float g_scores[(size_t)NH * SEQ * SEQ];  // 512 MB

// ============================================================
// Generic C[M,N] = A[M,K] * B[N,K]^T  (row-major, all dims %64==0, K%16==0)
// 64x64 tile, 16x16 threads, 4x4 micro-tile per thread.
// ============================================================
__global__ void gemm_tn(const float* __restrict__ A, const float* __restrict__ B,
                        float* __restrict__ C, int M, int N, int K) {
    __shared__ float As[16][68];
    __shared__ float Bs[16][68];
    const int tx = threadIdx.x, ty = threadIdx.y;
    const int tid = ty * 16 + tx;
    const int m0 = blockIdx.y * 64, n0 = blockIdx.x * 64;
    const int lrow = tid >> 2;          // 0..63
    const int lcol = (tid & 3) << 2;    // 0,4,8,12

    float acc[4][4] = {};
    for (int k0 = 0; k0 < K; k0 += 16) {
        float4 a = *(const float4*)(A + (size_t)(m0 + lrow) * K + k0 + lcol);
        float4 b = *(const float4*)(B + (size_t)(n0 + lrow) * K + k0 + lcol);
        As[lcol + 0][lrow] = a.x; As[lcol + 1][lrow] = a.y;
        As[lcol + 2][lrow] = a.z; As[lcol + 3][lrow] = a.w;
        Bs[lcol + 0][lrow] = b.x; Bs[lcol + 1][lrow] = b.y;
        Bs[lcol + 2][lrow] = b.z; Bs[lcol + 3][lrow] = b.w;
        __syncthreads();
        #pragma unroll
        for (int kk = 0; kk < 16; kk++) {
            float av[4], bv[4];
            #pragma unroll
            for (int i = 0; i < 4; i++) { av[i] = As[kk][ty * 4 + i]; bv[i] = Bs[kk][tx * 4 + i]; }
            #pragma unroll
            for (int i = 0; i < 4; i++)
                #pragma unroll
                for (int j = 0; j < 4; j++) acc[i][j] += av[i] * bv[j];
        }
        __syncthreads();
    }
    #pragma unroll
    for (int i = 0; i < 4; i++) {
        const int m = m0 + ty * 4 + i;
        #pragma unroll
        for (int j = 0; j < 4; j++)
            C[(size_t)m * N + n0 + tx * 4 + j] = acc[i][j];
    }
}

// ============================================================
// RoPE (interleaved pairs), matching the jnp reference in fp32.
// t: [SEQ, H, 128] contiguous. One thread per (s,h,pair).
// ============================================================
__global__ void rope_kernel(float* __restrict__ t, int H, int total) {
    int idx = blockIdx.x * blockDim.x + threadIdx.x;
    if (idx >= total) return;
    int i = idx & 63;
    int h = (idx >> 6) % H;
    int s = idx / (64 * H);
    float freq = __powf(500000.0f, -(float)i * (1.0f / 64.0f));
    float ang = (float)s * freq;
    float sn, cs;
    sincosf(ang, &sn, &cs);
    float* p = t + ((size_t)s * H + h) * HD + 2 * i;
    float x0 = p[0], x1 = p[1];
    p[0] = x0 * cs - x1 * sn;
    p[1] = x0 * sn + x1 * cs;
}

// ============================================================
// scores[h][s][t] = (q_h[s] . k_{h/4}[t]) / sqrt(128), causal mask.
// 64x64 tile per block; skip tiles entirely above the diagonal.
// ============================================================
__global__ void scores_kernel(const float* __restrict__ q, const float* __restrict__ k) {
    const int h = blockIdx.z;
    const int kv = h >> 2;
    const int s0 = blockIdx.y * 64, t0 = blockIdx.x * 64;
    if (t0 > s0 + 63) return;  // fully masked tile (uniform block exit)

    __shared__ float As[16][68];
    __shared__ float Bs[16][68];
    const int tx = threadIdx.x, ty = threadIdx.y;
    const int tid = ty * 16 + tx;
    const int lrow = tid >> 2;
    const int lcol = (tid & 3) << 2;

    const float* qb = q + (size_t)h * HD;
    const float* kb = k + (size_t)kv * HD;

    float acc[4][4] = {};
    for (int k0 = 0; k0 < HD; k0 += 16) {
        float4 a = *(const float4*)(qb + (size_t)(s0 + lrow) * DIM + k0 + lcol);
        float4 b = *(const float4*)(kb + (size_t)(t0 + lrow) * KVD + k0 + lcol);
        As[lcol + 0][lrow] = a.x; As[lcol + 1][lrow] = a.y;
        As[lcol + 2][lrow] = a.z; As[lcol + 3][lrow] = a.w;
        Bs[lcol + 0][lrow] = b.x; Bs[lcol + 1][lrow] = b.y;
        Bs[lcol + 2][lrow] = b.z; Bs[lcol + 3][lrow] = b.w;
        __syncthreads();
        #pragma unroll
        for (int kk = 0; kk < 16; kk++) {
            float av[4], bv[4];
            #pragma unroll
            for (int i = 0; i < 4; i++) { av[i] = As[kk][ty * 4 + i]; bv[i] = Bs[kk][tx * 4 + i]; }
            #pragma unroll
            for (int i = 0; i < 4; i++)
                #pragma unroll
                for (int j = 0; j < 4; j++) acc[i][j] += av[i] * bv[j];
        }
        __syncthreads();
    }

    const float scale = 0.08838834764831845f;   // 1/sqrt(128)
    const float ninf = __int_as_float(0xff800000);
    #pragma unroll
    for (int i = 0; i < 4; i++) {
        const int s = s0 + ty * 4 + i;
        #pragma unroll
        for (int j = 0; j < 4; j++) {
            const int t = t0 + tx * 4 + j;
            float val = acc[i][j] * scale;
            g_scores[((size_t)h * SEQ + s) * SEQ + t] = (t <= s) ? val : ninf;
        }
    }
}

// ============================================================
// Row softmax over t in [0, s]; zero the masked tail so PV is a plain GEMM.
// One block (256 thr) per (s, h).
// ============================================================
__global__ void softmax_kernel() {
    const int s = blockIdx.x;
    const int h = blockIdx.y;
    float* row = g_scores + ((size_t)h * SEQ + s) * SEQ;
    const int len = s + 1;
    const int tid = threadIdx.x;
    __shared__ float red[256];

    float mx = -3.402823466e38f;
    for (int t = tid; t < len; t += 256) mx = fmaxf(mx, row[t]);
    red[tid] = mx; __syncthreads();
    for (int o = 128; o > 0; o >>= 1) { if (tid < o) red[tid] = fmaxf(red[tid], red[tid + o]); __syncthreads(); }
    mx = red[0]; __syncthreads();

    float sum = 0.f;
    for (int t = tid; t < len; t += 256) { float e = __expf(row[t] - mx); row[t] = e; sum += e; }
    red[tid] = sum; __syncthreads();
    for (int o = 128; o > 0; o >>= 1) { if (tid < o) red[tid] += red[tid + o]; __syncthreads(); }
    const float inv = 1.0f / red[0];

    for (int t = tid; t < len; t += 256) row[t] *= inv;
    for (int t = len + tid; t < SEQ; t += 256) row[t] = 0.f;
}

// ============================================================
// attn[s, h*128+d] = sum_t probs[h][s][t] * v[t, kv*128+d]
// NN GEMM per head, K-loop truncated at the diagonal tile.
// ============================================================
__global__ void pv_kernel(const float* __restrict__ v, float* __restrict__ attn) {
    const int h = blockIdx.z, kv = h >> 2;
    const int s0 = blockIdx.y * 64, n0 = blockIdx.x * 64;
    const float* P = g_scores + (size_t)h * SEQ * SEQ;

    __shared__ float As[16][68];
    __shared__ float Bs[16][68];
    const int tx = threadIdx.x, ty = threadIdx.y;
    const int tid = ty * 16 + tx;
    const int arow = tid >> 2,  acol = (tid & 3) << 2;   // A tile 64x16
    const int brow = tid >> 4,  bcol = (tid & 15) << 2;  // B tile 16x64

    float acc[4][4] = {};
    const int kmax = s0 + 64;   // probs are zero beyond the diagonal
    for (int k0 = 0; k0 < kmax; k0 += 16) {
        float4 a = *(const float4*)(P + (size_t)(s0 + arow) * SEQ + k0 + acol);
        As[acol + 0][arow] = a.x; As[acol + 1][arow] = a.y;
        As[acol + 2][arow] = a.z; As[acol + 3][arow] = a.w;
        float4 b = *(const float4*)(v + (size_t)(k0 + brow) * KVD + kv * HD + n0 + bcol);
        *(float4*)&Bs[brow][bcol] = b;
        __syncthreads();
        #pragma unroll
        for (int kk = 0; kk < 16; kk++) {
            float av[4], bv[4];
            #pragma unroll
            for (int i = 0; i < 4; i++) { av[i] = As[kk][ty * 4 + i]; bv[i] = Bs[kk][tx * 4 + i]; }
            #pragma unroll
            for (int i = 0; i < 4; i++)
                #pragma unroll
                for (int j = 0; j < 4; j++) acc[i][j] += av[i] * bv[j];
        }
        __syncthreads();
    }
    #pragma unroll
    for (int i = 0; i < 4; i++) {
        const int s = s0 + ty * 4 + i;
        #pragma unroll
        for (int j = 0; j < 4; j++)
            attn[(size_t)s * DIM + h * HD + n0 + tx * 4 + j] = acc[i][j];
    }
}

// ============================================================
extern "C" void kernel_launch(void* const* d_in, const int* in_sizes, int n_in,
                              void* d_out, int out_size) {
    (void)in_sizes; (void)n_in; (void)out_size;
    const float* x  = (const float*)d_in[0];
    const float* wq = (const float*)d_in[1];
    const float* wk = (const float*)d_in[2];
    const float* wv = (const float*)d_in[3];
    const float* wo = (const float*)d_in[4];
    float* out = (float*)d_out;

    float *q, *k, *v, *attn;
    cudaGetSymbolAddress((void**)&q, g_q);
    cudaGetSymbolAddress((void**)&k, g_k);
    cudaGetSymbolAddress((void**)&v, g_v);
    cudaGetSymbolAddress((void**)&attn, g_attn);

    dim3 blk(16, 16);

    // Projections
    gemm_tn<<<dim3(DIM / 64, SEQ / 64), blk>>>(x, wq, q, SEQ, DIM, DIM);
    gemm_tn<<<dim3(KVD / 64, SEQ / 64), blk>>>(x, wk, k, SEQ, KVD, DIM);
    gemm_tn<<<dim3(KVD / 64, SEQ / 64), blk>>>(x, wv, v, SEQ, KVD, DIM);

    // RoPE on q and k
    const int tq = SEQ * NH * 64;
    const int tk = SEQ * NKV * 64;
    rope_kernel<<<(tq + 255) / 256, 256>>>(q, NH, tq);
    rope_kernel<<<(tk + 255) / 256, 256>>>(k, NKV, tk);

    // Attention
    scores_kernel<<<dim3(SEQ / 64, SEQ / 64, NH), blk>>>(q, k);
    softmax_kernel<<<dim3(SEQ, NH), 256>>>();
    pv_kernel<<<dim3(HD / 64, SEQ / 64, NH), blk>>>(v, attn);

    // Output projection
    gemm_tn<<<dim3(DIM / 64, SEQ / 64), blk>>>(attn, wo, out, SEQ, DIM, DIM);
}

// round 2
// speedup vs baseline: 1.0945x; 1.0945x over previous
#include <cuda_runtime.h>
#include <mma.h>
#include <math.h>

using namespace nvcuda;

#define SEQ 2048
#define DIM 4096
#define NH 32
#define NKV 8
#define HD 128
#define KVD (NKV*HD)   // 1024

// ---- scratch (no cudaMalloc allowed) ----
__device__ float g_q[SEQ * DIM];            // 32 MB
__device__ float g_k[SEQ * KVD];            // 8 MB
__device__ float g_v[SEQ * KVD];            // 8 MB
__device__ float g_attn[SEQ * DIM];         // 32 MB
__device__ float g_scores[(size_t)NH * SEQ * SEQ];  // 512 MB

#define ASTRIDE 24     // 16 + 8 pad (keeps 16B alignment at kk=8)
#define BSTRIDE2 132   // 128 + 4 pad for NN B tiles

__device__ __forceinline__ float4 to_tf32_4(float4 v) {
    v.x = wmma::__float_to_tf32(v.x);
    v.y = wmma::__float_to_tf32(v.y);
    v.z = wmma::__float_to_tf32(v.z);
    v.w = wmma::__float_to_tf32(v.w);
    return v;
}

// ============================================================
// TF32 WMMA core: 128x128 block tile, 8 warps as 4(m) x 2(n),
// each warp 32x64 = 2x4 fragments of m16n16k8. K-step 16.
// Both A and B tiles staged as [row][k] (TN layout).
// ============================================================
#define WMMA_TN_BODY(APTR, LDA, BPTR, LDB, KLEN)                                   \
    __shared__ float As[128 * ASTRIDE];                                            \
    __shared__ float Bs[128 * ASTRIDE];                                            \
    const int tid = threadIdx.x;                                                   \
    const int warp = tid >> 5;                                                     \
    const int wm = warp >> 1;                                                      \
    const int wn = warp & 1;                                                       \
    wmma::fragment<wmma::accumulator,16,16,8,float> acc[2][4];                     \
    _Pragma("unroll")                                                              \
    for (int i = 0; i < 2; i++)                                                    \
        _Pragma("unroll")                                                          \
        for (int j = 0; j < 4; j++) wmma::fill_fragment(acc[i][j], 0.0f);          \
    for (int k0 = 0; k0 < (KLEN); k0 += 16) {                                      \
        _Pragma("unroll")                                                          \
        for (int it = 0; it < 2; it++) {                                           \
            int vid = tid + it * 256;                                              \
            int r = vid >> 2, cc = (vid & 3) << 2;                                 \
            float4 a = to_tf32_4(*(const float4*)((APTR) + (size_t)(m0 + r) * (LDA) + k0 + cc)); \
            float4 b = to_tf32_4(*(const float4*)((BPTR) + (size_t)(n0 + r) * (LDB) + k0 + cc)); \
            *(float4*)&As[r * ASTRIDE + cc] = a;                                   \
            *(float4*)&Bs[r * ASTRIDE + cc] = b;                                   \
        }                                                                          \
        __syncthreads();                                                           \
        _Pragma("unroll")                                                          \
        for (int kk = 0; kk < 16; kk += 8) {                                       \
            wmma::fragment<wmma::matrix_a,16,16,8,wmma::precision::tf32,wmma::row_major> af[2]; \
            wmma::fragment<wmma::matrix_b,16,16,8,wmma::precision::tf32,wmma::col_major> bf[4]; \
            _Pragma("unroll")                                                      \
            for (int i = 0; i < 2; i++)                                            \
                wmma::load_matrix_sync(af[i], &As[(wm * 32 + i * 16) * ASTRIDE + kk], ASTRIDE); \
            _Pragma("unroll")                                                      \
            for (int j = 0; j < 4; j++)                                            \
                wmma::load_matrix_sync(bf[j], &Bs[(wn * 64 + j * 16) * ASTRIDE + kk], ASTRIDE); \
            _Pragma("unroll")                                                      \
            for (int i = 0; i < 2; i++)                                            \
                _Pragma("unroll")                                                  \
                for (int j = 0; j < 4; j++)                                        \
                    wmma::mma_sync(acc[i][j], af[i], bf[j], acc[i][j]);            \
        }                                                                          \
        __syncthreads();                                                           \
    }

// ---- C[M,N] = A[M,K] * B[N,K]^T : projections + output projection ----
__global__ __launch_bounds__(256) void wmma_gemm_tn(
    const float* __restrict__ A, const float* __restrict__ B,
    float* __restrict__ C, int N, int K) {
    const int m0 = blockIdx.y * 128, n0 = blockIdx.x * 128;
    WMMA_TN_BODY(A, K, B, K, K)
    #pragma unroll
    for (int i = 0; i < 2; i++)
        #pragma unroll
        for (int j = 0; j < 4; j++)
            wmma::store_matrix_sync(C + (size_t)(m0 + wm * 32 + i * 16) * N + n0 + wn * 64 + j * 16,
                                    acc[i][j], N, wmma::mem_row_major);
}

// ---- scores[h][s][t] = q_h[s] . k_{h/4}[t]  (unscaled, unmasked) ----
__global__ __launch_bounds__(256) void wmma_scores(
    const float* __restrict__ q, const float* __restrict__ k) {
    const int h = blockIdx.z, kv = h >> 2;
    const int m0 = blockIdx.y * 128, n0 = blockIdx.x * 128;  // m0=s, n0=t
    if (n0 >= m0 + 128) return;  // fully above diagonal
    const float* A = q + (size_t)h * HD;
    const float* B = k + (size_t)kv * HD;
    float* C = g_scores + (size_t)h * SEQ * SEQ;
    WMMA_TN_BODY(A, DIM, B, KVD, HD)
    #pragma unroll
    for (int i = 0; i < 2; i++)
        #pragma unroll
        for (int j = 0; j < 4; j++)
            wmma::store_matrix_sync(C + (size_t)(m0 + wm * 32 + i * 16) * SEQ + n0 + wn * 64 + j * 16,
                                    acc[i][j], SEQ, wmma::mem_row_major);
}

// ---- attn[s, h*128+d] = sum_t P[h][s][t] * v[t, kv*128+d]  (NN) ----
__global__ __launch_bounds__(256) void wmma_pv(
    const float* __restrict__ v, float* __restrict__ attn) {
    const int h = blockIdx.z, kv = h >> 2;
    const int m0 = blockIdx.y * 128;   // s-tile; N tile = full 128 (HD)
    const float* P = g_scores + (size_t)h * SEQ * SEQ;
    const float* V = v + (size_t)kv * HD;

    __shared__ float As[128 * ASTRIDE];
    __shared__ float Bs[16 * BSTRIDE2];
    const int tid = threadIdx.x;
    const int warp = tid >> 5;
    const int wm = warp >> 1;
    const int wn = warp & 1;
    wmma::fragment<wmma::accumulator,16,16,8,float> acc[2][4];
    #pragma unroll
    for (int i = 0; i < 2; i++)
        #pragma unroll
        for (int j = 0; j < 4; j++) wmma::fill_fragment(acc[i][j], 0.0f);

    const int kmax = m0 + 128;   // probs zero beyond diagonal tile
    for (int k0 = 0; k0 < kmax; k0 += 16) {
        #pragma unroll
        for (int it = 0; it < 2; it++) {
            int vid = tid + it * 256;
            // A: P tile 128 rows x 16 k
            int r = vid >> 2, cc = (vid & 3) << 2;
            float4 a = to_tf32_4(*(const float4*)(P + (size_t)(m0 + r) * SEQ + k0 + cc));
            *(float4*)&As[r * ASTRIDE + cc] = a;
            // B: V tile 16 k x 128 cols
            int br = vid >> 5, bc = (vid & 31) << 2;
            float4 b = to_tf32_4(*(const float4*)(V + (size_t)(k0 + br) * KVD + bc));
            *(float4*)&Bs[br * BSTRIDE2 + bc] = b;
        }
        __syncthreads();
        #pragma unroll
        for (int kk = 0; kk < 16; kk += 8) {
            wmma::fragment<wmma::matrix_a,16,16,8,wmma::precision::tf32,wmma::row_major> af[2];
            wmma::fragment<wmma::matrix_b,16,16,8,wmma::precision::tf32,wmma::row_major> bf[4];
            #pragma unroll
            for (int i = 0; i < 2; i++)
                wmma::load_matrix_sync(af[i], &As[(wm * 32 + i * 16) * ASTRIDE + kk], ASTRIDE);
            #pragma unroll
            for (int j = 0; j < 4; j++)
                wmma::load_matrix_sync(bf[j], &Bs[kk * BSTRIDE2 + wn * 64 + j * 16], BSTRIDE2);
            #pragma unroll
            for (int i = 0; i < 2; i++)
                #pragma unroll
                for (int j = 0; j < 4; j++)
                    wmma::mma_sync(acc[i][j], af[i], bf[j], acc[i][j]);
        }
        __syncthreads();
    }
    #pragma unroll
    for (int i = 0; i < 2; i++)
        #pragma unroll
        for (int j = 0; j < 4; j++)
            wmma::store_matrix_sync(attn + (size_t)(m0 + wm * 32 + i * 16) * DIM + h * HD + wn * 64 + j * 16,
                                    acc[i][j], DIM, wmma::mem_row_major);
}

// ============================================================
// RoPE (interleaved pairs), fp32, matching the jnp reference.
// ============================================================
__global__ void rope_kernel(float* __restrict__ t, int H, int total) {
    int idx = blockIdx.x * blockDim.x + threadIdx.x;
    if (idx >= total) return;
    int i = idx & 63;
    int h = (idx >> 6) % H;
    int s = idx / (64 * H);
    float freq = __powf(500000.0f, -(float)i * (1.0f / 64.0f));
    float ang = (float)s * freq;
    float sn, cs;
    sincosf(ang, &sn, &cs);
    float* p = t + ((size_t)s * H + h) * HD + 2 * i;
    float x0 = p[0], x1 = p[1];
    p[0] = x0 * cs - x1 * sn;
    p[1] = x0 * sn + x1 * cs;
}

// ============================================================
// Softmax with scale + causal mask folded in.
// Reads raw dot products; writes probs, zeroes the masked tail.
// ============================================================
__global__ void softmax_kernel() {
    const int s = blockIdx.x;
    const int h = blockIdx.y;
    float* row = g_scores + ((size_t)h * SEQ + s) * SEQ;
    const int len = s + 1;
    const int tid = threadIdx.x;
    const float scale = 0.08838834764831845f;   // 1/sqrt(128)
    __shared__ float red[256];

    float mx = -3.402823466e38f;
    for (int t = tid; t < len; t += 256) mx = fmaxf(mx, row[t] * scale);
    red[tid] = mx; __syncthreads();
    for (int o = 128; o > 0; o >>= 1) { if (tid < o) red[tid] = fmaxf(red[tid], red[tid + o]); __syncthreads(); }
    mx = red[0]; __syncthreads();

    float sum = 0.f;
    for (int t = tid; t < len; t += 256) { float e = __expf(row[t] * scale - mx); row[t] = e; sum += e; }
    red[tid] = sum; __syncthreads();
    for (int o = 128; o > 0; o >>= 1) { if (tid < o) red[tid] += red[tid + o]; __syncthreads(); }
    const float inv = 1.0f / red[0];

    for (int t = tid; t < len; t += 256) row[t] *= inv;
    for (int t = len + tid; t < SEQ; t += 256) row[t] = 0.f;
}

// ============================================================
extern "C" void kernel_launch(void* const* d_in, const int* in_sizes, int n_in,
                              void* d_out, int out_size) {
    (void)in_sizes; (void)n_in; (void)out_size;
    const float* x  = (const float*)d_in[0];
    const float* wq = (const float*)d_in[1];
    const float* wk = (const float*)d_in[2];
    const float* wv = (const float*)d_in[3];
    const float* wo = (const float*)d_in[4];
    float* out = (float*)d_out;

    float *q, *k, *v, *attn;
    cudaGetSymbolAddress((void**)&q, g_q);
    cudaGetSymbolAddress((void**)&k, g_k);
    cudaGetSymbolAddress((void**)&v, g_v);
    cudaGetSymbolAddress((void**)&attn, g_attn);

    // Projections (TF32 tensor-core GEMMs)
    wmma_gemm_tn<<<dim3(DIM / 128, SEQ / 128), 256>>>(x, wq, q, DIM, DIM);
    wmma_gemm_tn<<<dim3(KVD / 128, SEQ / 128), 256>>>(x, wk, k, KVD, DIM);
    wmma_gemm_tn<<<dim3(KVD / 128, SEQ / 128), 256>>>(x, wv, v, KVD, DIM);

    // RoPE on q and k
    const int tq = SEQ * NH * 64;
    const int tk = SEQ * NKV * 64;
    rope_kernel<<<(tq + 255) / 256, 256>>>(q, NH, tq);
    rope_kernel<<<(tk + 255) / 256, 256>>>(k, NKV, tk);

    // Attention
    wmma_scores<<<dim3(SEQ / 128, SEQ / 128, NH), 256>>>(q, k);
    softmax_kernel<<<dim3(SEQ, NH), 256>>>();
    wmma_pv<<<dim3(1, SEQ / 128, NH), 256>>>(v, attn);

    // Output projection
    wmma_gemm_tn<<<dim3(DIM / 128, SEQ / 128), 256>>>(attn, wo, out, DIM, DIM);
}

// round 4
// speedup vs baseline: 1.9940x; 1.8219x over previous
#include <cuda_runtime.h>
#include <cuda_bf16.h>
#include <mma.h>
#include <stdint.h>
#include <math.h>

using namespace nvcuda;

#define SEQ 2048
#define DIM 4096
#define NH 32
#define NKV 8
#define HD 128
#define KVD (NKV*HD)   // 1024

typedef __nv_bfloat16 bf16;

// ================= scratch (no cudaMalloc allowed) =================
__device__ float g_q[SEQ * DIM];
__device__ float g_k[SEQ * KVD];
__device__ float g_v[SEQ * KVD];
__device__ float g_scores[(size_t)NH * SEQ * SEQ];              // 512 MB
__device__ bf16 g_xh[SEQ * DIM],  g_xl[SEQ * DIM];
__device__ bf16 g_wqh[DIM * DIM], g_wql[DIM * DIM];
__device__ bf16 g_wkh[KVD * DIM], g_wkl[KVD * DIM];
__device__ bf16 g_wvh[KVD * DIM], g_wvl[KVD * DIM];
__device__ bf16 g_woh[DIM * DIM], g_wol[DIM * DIM];
__device__ bf16 g_qh[SEQ * DIM],  g_ql[SEQ * DIM];
__device__ bf16 g_kh[SEQ * KVD],  g_kl[SEQ * KVD];
__device__ bf16 g_vth[KVD * SEQ], g_vtl[KVD * SEQ];             // V transposed
__device__ bf16 g_ph[(size_t)NH * SEQ * SEQ], g_pl[(size_t)NH * SEQ * SEQ];
__device__ bf16 g_ah[SEQ * DIM],  g_al[SEQ * DIM];

// ================= cp.async helpers =================
__device__ __forceinline__ void cpa16(uint32_t dst, const void* src) {
    unsigned long long g = (unsigned long long)__cvta_generic_to_global(src);
    asm volatile("cp.async.cg.shared.global [%0], [%1], 16;" :: "r"(dst), "l"(g) : "memory");
}
#define CPA_COMMIT() asm volatile("cp.async.commit_group;" ::: "memory")
#define CPA_WAIT(n)  asm volatile("cp.async.wait_group %0;" :: "n"(n) : "memory")

// ================= 3-pass bf16 HMMA GEMM =================
// C[M,N] = Ah*Bh^T + Ah*Bl^T + Al*Bh^T   (TN, row-major, 128x128 CTA tiles)
// MODE 0: generic, fp32 C.
// MODE 1: scores (per-head, causal tile skip), fp32 C.
// MODE 2: PV (per-head, K truncated at diagonal), bf16 hi/lo C.
//
// smem: double-buffered chunks of K=32.  Each chunk holds 4 tiles
// (Ah, Al, Bh, Bl), each 128 rows x 32 bf16 with row stride 40 (80B).
#define TSTRIDE 40
#define TILE_E  (128 * TSTRIDE)          // elements per tile (5120)
#define CHUNK_E (4 * TILE_E)             // elements per buffer (20480)
#define GSMEM   (2 * CHUNK_E * 2)        // bytes (81920)

template<int MODE>
__global__ void __launch_bounds__(256) gemm3_kernel(
    const bf16* __restrict__ Ah, const bf16* __restrict__ Al,
    const bf16* __restrict__ Bh, const bf16* __restrict__ Bl,
    float* __restrict__ Cf, bf16* __restrict__ Ch, bf16* __restrict__ Cl,
    int K, int lda, int ldb, int ldc)
{
    const int m0 = blockIdx.y * 128;
    const int n0 = blockIdx.x * 128;
    if (MODE == 1 && n0 > m0) return;   // tile fully above diagonal
    const int h = blockIdx.z, kvh = h >> 2;
    const int tid = threadIdx.x;
    const int warp = tid >> 5;
    const int wm = warp >> 1;           // 0..3  (32-row slice)
    const int wn = warp & 1;            // 0..1  (64-col slice)

    size_t aoff, boff, coff = 0;
    int kLen = K;
    if (MODE == 0)      { aoff = (size_t)m0 * lda;                         boff = (size_t)n0 * ldb; }
    else if (MODE == 1) { aoff = (size_t)m0 * lda + (size_t)h * HD;        boff = (size_t)n0 * ldb + (size_t)kvh * HD;
                          coff = (size_t)h * SEQ * SEQ; }
    else                { aoff = (size_t)h * SEQ * SEQ + (size_t)m0 * lda; boff = (size_t)(kvh * HD) * ldb;
                          kLen = m0 + 128; }
    const bf16* pAh = Ah + aoff; const bf16* pAl = Al + aoff;
    const bf16* pBh = Bh + boff; const bf16* pBl = Bl + boff;

    extern __shared__ __align__(16) char dsm[];
    bf16* smem = (bf16*)dsm;
    const uint32_t sm_u32 = (uint32_t)__cvta_generic_to_shared(dsm);

    wmma::fragment<wmma::accumulator, 16, 16, 16, float> acc[2][4];
    #pragma unroll
    for (int i = 0; i < 2; i++)
        #pragma unroll
        for (int j = 0; j < 4; j++) wmma::fill_fragment(acc[i][j], 0.0f);

    const int NC = kLen >> 5;   // K chunks of 32

    // each thread loads 2x16B per tile: row = tid>>1, segs {0,1} or {2,3}
    const int lrow = tid >> 1;
    const int lseg = (tid & 1) * 2;

    auto load_chunk = [&](int buf, int ko) {
        const uint32_t b = sm_u32 + buf * CHUNK_E * 2;
        const uint32_t soff = (uint32_t)(lrow * TSTRIDE + lseg * 8) * 2;
        const bf16* srcs[4] = { pAh + ko, pAl + ko, pBh + ko, pBl + ko };
        const int lds[4] = { lda, lda, ldb, ldb };
        #pragma unroll
        for (int t = 0; t < 4; t++) {
            const bf16* g = srcs[t] + (size_t)lrow * lds[t] + lseg * 8;
            const uint32_t d = b + t * TILE_E * 2 + soff;
            cpa16(d, g);
            cpa16(d + 16, g + 8);
        }
    };

    load_chunk(0, 0);
    CPA_COMMIT();

    for (int c = 0; c < NC; ++c) {
        if (c + 1 < NC) {
            load_chunk((c + 1) & 1, (c + 1) << 5);
            CPA_COMMIT();
            CPA_WAIT(1);
        } else {
            CPA_WAIT(0);
        }
        __syncthreads();

        const bf16* sb = smem + (c & 1) * CHUNK_E;
        const bf16* sAh = sb;
        const bf16* sAl = sb + TILE_E;
        const bf16* sBh = sb + 2 * TILE_E;
        const bf16* sBl = sb + 3 * TILE_E;

        #pragma unroll
        for (int kk = 0; kk < 32; kk += 16) {
            wmma::fragment<wmma::matrix_a, 16, 16, 16, bf16, wmma::row_major> ah[2], al[2];
            wmma::fragment<wmma::matrix_b, 16, 16, 16, bf16, wmma::col_major> bh[4], bl[4];
            #pragma unroll
            for (int i = 0; i < 2; i++) {
                wmma::load_matrix_sync(ah[i], sAh + (wm * 32 + i * 16) * TSTRIDE + kk, TSTRIDE);
                wmma::load_matrix_sync(al[i], sAl + (wm * 32 + i * 16) * TSTRIDE + kk, TSTRIDE);
            }
            #pragma unroll
            for (int j = 0; j < 4; j++) {
                wmma::load_matrix_sync(bh[j], sBh + (wn * 64 + j * 16) * TSTRIDE + kk, TSTRIDE);
                wmma::load_matrix_sync(bl[j], sBl + (wn * 64 + j * 16) * TSTRIDE + kk, TSTRIDE);
            }
            #pragma unroll
            for (int i = 0; i < 2; i++)
                #pragma unroll
                for (int j = 0; j < 4; j++) {
                    wmma::mma_sync(acc[i][j], ah[i], bh[j], acc[i][j]);
                    wmma::mma_sync(acc[i][j], ah[i], bl[j], acc[i][j]);
                    wmma::mma_sync(acc[i][j], al[i], bh[j], acc[i][j]);
                }
        }
        __syncthreads();
    }

    if (MODE != 2) {
        float* C = Cf + coff;
        #pragma unroll
        for (int i = 0; i < 2; i++)
            #pragma unroll
            for (int j = 0; j < 4; j++)
                wmma::store_matrix_sync(C + (size_t)(m0 + wm * 32 + i * 16) * ldc + n0 + wn * 64 + j * 16,
                                        acc[i][j], ldc, wmma::mem_row_major);
    } else {
        // stage fp32 in smem, then split-write bf16 hi/lo
        float* st = (float*)dsm;
        #pragma unroll
        for (int i = 0; i < 2; i++)
            #pragma unroll
            for (int j = 0; j < 4; j++)
                wmma::store_matrix_sync(st + (wm * 32 + i * 16) * 128 + wn * 64 + j * 16,
                                        acc[i][j], 128, wmma::mem_row_major);
        __syncthreads();
        const int r = tid >> 1;
        const int c0 = (tid & 1) * 64;
        const size_t off = (size_t)(m0 + r) * ldc + (size_t)h * HD + c0;
        #pragma unroll
        for (int cc = 0; cc < 64; cc += 2) {
            float v0 = st[r * 128 + c0 + cc], v1 = st[r * 128 + c0 + cc + 1];
            bf16 h0 = __float2bfloat16(v0), h1 = __float2bfloat16(v1);
            bf16 l0 = __float2bfloat16(v0 - __bfloat162float(h0));
            bf16 l1 = __float2bfloat16(v1 - __bfloat162float(h1));
            *(__nv_bfloat162*)(Ch + off + cc) = __halves2bfloat162(h0, h1);
            *(__nv_bfloat162*)(Cl + off + cc) = __halves2bfloat162(l0, l1);
        }
    }
}

// ================= small kernels =================
__global__ void split_kernel(const float4* __restrict__ s, __nv_bfloat162* __restrict__ h2,
                             __nv_bfloat162* __restrict__ l2, int n4) {
    int i = blockIdx.x * 256 + threadIdx.x;
    if (i >= n4) return;
    float4 v = s[i];
    bf16 a = __float2bfloat16(v.x), b = __float2bfloat16(v.y);
    bf16 c = __float2bfloat16(v.z), d = __float2bfloat16(v.w);
    h2[2*i]   = __halves2bfloat162(a, b);
    h2[2*i+1] = __halves2bfloat162(c, d);
    l2[2*i]   = __halves2bfloat162(__float2bfloat16(v.x - __bfloat162float(a)),
                                   __float2bfloat16(v.y - __bfloat162float(b)));
    l2[2*i+1] = __halves2bfloat162(__float2bfloat16(v.z - __bfloat162float(c)),
                                   __float2bfloat16(v.w - __bfloat162float(d)));
}

__global__ void rope_split_kernel(const float* __restrict__ src, bf16* __restrict__ dh,
                                  bf16* __restrict__ dl, int H, int total) {
    int idx = blockIdx.x * 256 + threadIdx.x;
    if (idx >= total) return;
    int i = idx & 63;
    int rest = idx >> 6;
    int h = rest % H;
    int s = rest / H;
    float freq = __powf(500000.0f, -(float)i * (1.0f / 64.0f));
    float ang = (float)s * freq;
    float sn, cs; sincosf(ang, &sn, &cs);
    size_t o = ((size_t)s * H + h) * HD + 2 * i;
    float x0 = src[o], x1 = src[o + 1];
    float r0 = x0 * cs - x1 * sn, r1 = x0 * sn + x1 * cs;
    bf16 h0 = __float2bfloat16(r0), h1 = __float2bfloat16(r1);
    dh[o] = h0; dh[o + 1] = h1;
    dl[o]     = __float2bfloat16(r0 - __bfloat162float(h0));
    dl[o + 1] = __float2bfloat16(r1 - __bfloat162float(h1));
}

__global__ void transpose_split_v(const float* __restrict__ v, bf16* __restrict__ th,
                                  bf16* __restrict__ tl) {
    __shared__ float t[32][33];
    const int d0 = blockIdx.x * 32, t0 = blockIdx.y * 32;
    const int tx = threadIdx.x, ty = threadIdx.y;
    #pragma unroll
    for (int j = 0; j < 32; j += 8)
        t[ty + j][tx] = v[(size_t)(t0 + ty + j) * KVD + d0 + tx];
    __syncthreads();
    #pragma unroll
    for (int j = 0; j < 32; j += 8) {
        float val = t[tx][ty + j];
        bf16 hh = __float2bfloat16(val);
        size_t o = (size_t)(d0 + ty + j) * SEQ + t0 + tx;
        th[o] = hh;
        tl[o] = __float2bfloat16(val - __bfloat162float(hh));
    }
}

// softmax over t in [0,s] (scale + mask inside); bf16 hi/lo probs out,
// tail zeroed to the 128 boundary so PV runs a truncated plain GEMM.
__global__ void softmax_kernel(const float* __restrict__ scores, bf16* __restrict__ ph,
                               bf16* __restrict__ pl) {
    const int s = blockIdx.x, h = blockIdx.y;
    const float* row = scores + ((size_t)h * SEQ + s) * SEQ;
    bf16* prh = ph + ((size_t)h * SEQ + s) * SEQ;
    bf16* prl = pl + ((size_t)h * SEQ + s) * SEQ;
    const int len = s + 1;
    const int zlen = ((s >> 7) + 1) << 7;
    const int tid = threadIdx.x;
    const float scale = 0.08838834764831845f;
    __shared__ float red[256];

    float mx = -3.402823466e38f;
    for (int t = tid; t < len; t += 256) mx = fmaxf(mx, row[t] * scale);
    red[tid] = mx; __syncthreads();
    for (int o = 128; o > 0; o >>= 1) { if (tid < o) red[tid] = fmaxf(red[tid], red[tid + o]); __syncthreads(); }
    mx = red[0]; __syncthreads();

    float sum = 0.f;
    for (int t = tid; t < len; t += 256) sum += __expf(row[t] * scale - mx);
    red[tid] = sum; __syncthreads();
    for (int o = 128; o > 0; o >>= 1) { if (tid < o) red[tid] += red[tid + o]; __syncthreads(); }
    const float inv = 1.0f / red[0];

    for (int t = tid; t < len; t += 256) {
        float p = __expf(row[t] * scale - mx) * inv;
        bf16 hh = __float2bfloat16(p);
        prh[t] = hh;
        prl[t] = __float2bfloat16(p - __bfloat162float(hh));
    }
    const bf16 z = __float2bfloat16(0.f);
    for (int t = len + tid; t < zlen; t += 256) { prh[t] = z; prl[t] = z; }
}

// ================= host =================
extern "C" void kernel_launch(void* const* d_in, const int* in_sizes, int n_in,
                              void* d_out, int out_size) {
    (void)in_sizes; (void)n_in; (void)out_size;
    const float* x  = (const float*)d_in[0];
    const float* wq = (const float*)d_in[1];
    const float* wk = (const float*)d_in[2];
    const float* wv = (const float*)d_in[3];
    const float* wo = (const float*)d_in[4];
    float* out = (float*)d_out;

    float *qf, *kf, *vf, *scores;
    bf16 *xh, *xl, *wqh, *wql, *wkh, *wkl, *wvh, *wvl, *woh, *wol;
    bf16 *qh, *ql, *kh, *kl, *vth, *vtl, *ph, *pl, *ah, *al;
    cudaGetSymbolAddress((void**)&qf, g_q);
    cudaGetSymbolAddress((void**)&kf, g_k);
    cudaGetSymbolAddress((void**)&vf, g_v);
    cudaGetSymbolAddress((void**)&scores, g_scores);
    cudaGetSymbolAddress((void**)&xh, g_xh);  cudaGetSymbolAddress((void**)&xl, g_xl);
    cudaGetSymbolAddress((void**)&wqh, g_wqh); cudaGetSymbolAddress((void**)&wql, g_wql);
    cudaGetSymbolAddress((void**)&wkh, g_wkh); cudaGetSymbolAddress((void**)&wkl, g_wkl);
    cudaGetSymbolAddress((void**)&wvh, g_wvh); cudaGetSymbolAddress((void**)&wvl, g_wvl);
    cudaGetSymbolAddress((void**)&woh, g_woh); cudaGetSymbolAddress((void**)&wol, g_wol);
    cudaGetSymbolAddress((void**)&qh, g_qh);  cudaGetSymbolAddress((void**)&ql, g_ql);
    cudaGetSymbolAddress((void**)&kh, g_kh);  cudaGetSymbolAddress((void**)&kl, g_kl);
    cudaGetSymbolAddress((void**)&vth, g_vth); cudaGetSymbolAddress((void**)&vtl, g_vtl);
    cudaGetSymbolAddress((void**)&ph, g_ph);  cudaGetSymbolAddress((void**)&pl, g_pl);
    cudaGetSymbolAddress((void**)&ah, g_ah);  cudaGetSymbolAddress((void**)&al, g_al);

    cudaFuncSetAttribute(gemm3_kernel<0>, cudaFuncAttributeMaxDynamicSharedMemorySize, GSMEM);
    cudaFuncSetAttribute(gemm3_kernel<1>, cudaFuncAttributeMaxDynamicSharedMemorySize, GSMEM);
    cudaFuncSetAttribute(gemm3_kernel<2>, cudaFuncAttributeMaxDynamicSharedMemorySize, GSMEM);

    // split inputs to bf16 hi/lo
    split_kernel<<<(SEQ*DIM/4 + 255)/256, 256>>>((const float4*)x,  (__nv_bfloat162*)xh,  (__nv_bfloat162*)xl,  SEQ*DIM/4);
    split_kernel<<<(DIM*DIM/4 + 255)/256, 256>>>((const float4*)wq, (__nv_bfloat162*)wqh, (__nv_bfloat162*)wql, DIM*DIM/4);
    split_kernel<<<(KVD*DIM/4 + 255)/256, 256>>>((const float4*)wk, (__nv_bfloat162*)wkh, (__nv_bfloat162*)wkl, KVD*DIM/4);
    split_kernel<<<(KVD*DIM/4 + 255)/256, 256>>>((const float4*)wv, (__nv_bfloat162*)wvh, (__nv_bfloat162*)wvl, KVD*DIM/4);
    split_kernel<<<(DIM*DIM/4 + 255)/256, 256>>>((const float4*)wo, (__nv_bfloat162*)woh, (__nv_bfloat162*)wol, DIM*DIM/4);

    // projections (3-pass bf16 HMMA)
    gemm3_kernel<0><<<dim3(DIM/128, SEQ/128), 256, GSMEM>>>(xh, xl, wqh, wql, qf, nullptr, nullptr, DIM, DIM, DIM, DIM);
    gemm3_kernel<0><<<dim3(KVD/128, SEQ/128), 256, GSMEM>>>(xh, xl, wkh, wkl, kf, nullptr, nullptr, DIM, DIM, DIM, KVD);
    gemm3_kernel<0><<<dim3(KVD/128, SEQ/128), 256, GSMEM>>>(xh, xl, wvh, wvl, vf, nullptr, nullptr, DIM, DIM, DIM, KVD);

    // rope + split
    rope_split_kernel<<<(SEQ*NH*64 + 255)/256, 256>>>(qf, qh, ql, NH, SEQ*NH*64);
    rope_split_kernel<<<(SEQ*NKV*64 + 255)/256, 256>>>(kf, kh, kl, NKV, SEQ*NKV*64);
    transpose_split_v<<<dim3(KVD/32, SEQ/32), dim3(32, 8)>>>(vf, vth, vtl);

    // attention
    gemm3_kernel<1><<<dim3(SEQ/128, SEQ/128, NH), 256, GSMEM>>>(qh, ql, kh, kl, scores, nullptr, nullptr, HD, DIM, KVD, SEQ);
    softmax_kernel<<<dim3(SEQ, NH), 256>>>(scores, ph, pl);
    gemm3_kernel<2><<<dim3(1, SEQ/128, NH), 256, GSMEM>>>(ph, pl, vth, vtl, nullptr, ah, al, 0, SEQ, SEQ, DIM);

    // output projection
    gemm3_kernel<0><<<dim3(DIM/128, SEQ/128), 256, GSMEM>>>(ah, al, woh, wol, out, nullptr, nullptr, DIM, DIM, DIM, DIM);
}